// round 13
// baseline (speedup 1.0000x reference)
#include <cuda_runtime.h>
#include <cstdint>

// ============================================================================
// OneHotEncoding — single kernel, zero grid barriers, block-local argmin.
// Base: R10 structure (best wall 31.5us). Single change this round:
// 2 points per thread in the stream (TILE 1024 -> 2048) to break the ILP=1
// serial LDS->ALU->LDS->FMA->LDS chain identified as the stream bottleneck.
// R12 lesson: do NOT force launch_bounds reg caps (spills) or shrink the
// block below the 128-wide build phase.
//
// Output layout (float32):
//   [0, 4L)            input_tensor: per point (x, y, z, one_hot)
//   [4L, 4L+3B)        closest_points [B,3]
//   [4L+3B, 4L+4B)     min_index as float [B]
//
// Merge key: ~((u64)d2bits<<32 | idx), combined with max.
//   - zero-initialized .bss g_best IS the identity (no init pass)
//   - max of complement == min (d2, idx) => first-index tie-break
//   - probe seed ~(probe_d2<<32 | 0xFFFFFFFF) is provably below the true
//     winner's key (true d2 <= probe d2; real idx < 0xFFFFFFFF): filters only.
//   - finalize resets g_best/g_done to 0 => graph-replay deterministic.
//
// Candidate table: receiver r's box [r-UB, r+UB]^3 (UB = exact distance to a
// real sampled point) covers r's true NN. Cells with >KCAP receivers get
// sentinel 255 => brute-force all B there. Unconditionally correct.
// ============================================================================

#define GC       16
#define CELLS    (GC * GC * GC)        // 4096
#define MAXB     128
#define GRID     152
#define THREADS  1024
#define KCAP     5                     // candidate list slots per cell
#define PROBE_N  512                   // sample points for UB probe
#define TILE     2048                  // points per tile (2 per thread)

__device__ unsigned long long g_best[MAXB];   // complemented keys; 0 = identity
__device__ unsigned int       g_done;         // zero-init; self-resetting

__device__ __forceinline__ int cell_of(float x) {
    int c = __float2int_rd(x * (float)GC);
    c = c < 0 ? 0 : c;
    return c > GC - 1 ? GC - 1 : c;
}

// ---------------------------------------------------------------------------
__global__ void __launch_bounds__(THREADS, 1)
fused_kernel(const float* __restrict__ pts, const float* __restrict__ recv,
             float* __restrict__ out, int L, int B)
{
    const int tid  = threadIdx.x;
    const int lane = tid & 31;
    const int wid  = tid >> 5;
    const int bid  = blockIdx.x;

    __shared__ float srx[MAXB], sry[MAXB], srz[MAXB];
    __shared__ float s_ub[MAXB];                       // probe min d2 per recv
    __shared__ unsigned long long s_best[MAXB];        // block-local keys
    __shared__ unsigned char s_list[CELLS * KCAP];     // 20 KB
    __shared__ unsigned char s_cnt[CELLS];             // 4 KB (255 = overflow)
    // 24 KB: SoA tile x/y/z[TILE]; also reused as probe SoA and cnt32
    __shared__ __align__(16) float s_mem[3 * TILE];

    float* t_x = s_mem;
    float* t_y = s_mem + TILE;
    float* t_z = s_mem + 2 * TILE;

    // ---- stage receivers ----
    if (tid < B) {
        srx[tid] = recv[3 * tid + 0];
        sry[tid] = recv[3 * tid + 1];
        srz[tid] = recv[3 * tid + 2];
    }

    // ---- stage probe samples SoA (512 points = 1536 floats) ----
    const int n  = (L < PROBE_N) ? L : PROBE_N;
    const int n3 = n * 3;
#pragma unroll
    for (int j = 0; j < 2; ++j) {
        int e = tid + j * THREADS;                 // [0, 2048)
        if (e < PROBE_N * 3) {
            float v = (e < n3) ? pts[e] : 1.0e30f;
            int p = e / 3, c = e - p * 3;
            if      (c == 0) t_x[p] = v;
            else if (c == 1) t_y[p] = v;
            else             t_z[p] = v;
        }
    }
    __syncthreads();

    // ---- UB probe: warp wid owns receivers [4*wid, 4*wid+4) ----
    {
        const int rbase = wid * 4;
        float rx[4], ry[4], rz[4], bd[4];
#pragma unroll
        for (int k = 0; k < 4; ++k) {
            int rb = rbase + k;
            rx[k] = (rb < B) ? srx[rb] : 0.f;
            ry[k] = (rb < B) ? sry[rb] : 0.f;
            rz[k] = (rb < B) ? srz[rb] : 0.f;
            bd[k] = 3.4e38f;
        }
#pragma unroll 4
        for (int j = 0; j < PROBE_N / 32; ++j) {
            int i = lane + 32 * j;
            float px = t_x[i];
            float py = t_y[i];
            float pz = t_z[i];
#pragma unroll
            for (int k = 0; k < 4; ++k) {
                float dx = px - rx[k];
                float dy = py - ry[k];
                float dz = pz - rz[k];
                float d2 = dx * dx + dy * dy + dz * dz;
                bd[k] = fminf(bd[k], d2);
            }
        }
#pragma unroll
        for (int k = 0; k < 4; ++k) {
#pragma unroll
            for (int m = 16; m > 0; m >>= 1)
                bd[k] = fminf(bd[k], __shfl_xor_sync(0xffffffffu, bd[k], m));
            if (lane == 0 && (rbase + k) < B) {
                s_ub[rbase + k] = bd[k];
                // seed: <= true winner's key (d2 >= true d2, idx field maximal)
                s_best[rbase + k] =
                    ~((((unsigned long long)__float_as_uint(bd[k])) << 32) |
                      0xFFFFFFFFull);
            }
        }
    }
    __syncthreads();

    // ---- zero cnt32 (reuses s_mem: 16 KB of 24 KB) ----
    unsigned int* cnt32 = reinterpret_cast<unsigned int*>(s_mem);
#pragma unroll
    for (int j = 0; j < CELLS / THREADS; ++j) cnt32[tid + j * THREADS] = 0u;
    __syncthreads();

    // ---- build candidate lists (receiver-major, smem atomics) ----
    if (tid < B) {
        float ub = sqrtf(s_ub[tid]) * 1.0001f + 1e-7f;   // ulp guard
        float rx = srx[tid], ry = sry[tid], rz = srz[tid];
        int lx = cell_of(rx - ub), hx = cell_of(rx + ub);
        int ly = cell_of(ry - ub), hy = cell_of(ry + ub);
        int lz = cell_of(rz - ub), hz = cell_of(rz + ub);
        for (int zz = lz; zz <= hz; ++zz)
            for (int yy = ly; yy <= hy; ++yy)
                for (int xx = lx; xx <= hx; ++xx) {
                    int c = (zz * GC + yy) * GC + xx;
                    unsigned int pos = atomicAdd(&cnt32[c], 1u);
                    if (pos < KCAP) s_list[c * KCAP + pos] = (unsigned char)tid;
                }
    }
    __syncthreads();

    // ---- compact counts to u8 with overflow sentinel ----
#pragma unroll
    for (int j = 0; j < CELLS / THREADS; ++j) {
        int c = tid + j * THREADS;
        unsigned int v = cnt32[c];
        s_cnt[c] = (v > KCAP) ? (unsigned char)255 : (unsigned char)v;
    }
    __syncthreads();

    // ---- streaming pass: SoA tiles, 2 points/thread (ILP=2) ----
    const int nTiles = (L + TILE - 1) / TILE;
    const int L3 = L * 3;

    for (int tile = bid; tile < nTiles; tile += GRID) {
        const int base = tile * TILE;
        __syncthreads();                 // previous tile fully consumed
#pragma unroll
        for (int j = 0; j < 6; ++j) {    // 6144 floats, coalesced scalar loads
            int e  = tid + j * THREADS;
            int ge = base * 3 + e;
            float v = (ge < L3) ? pts[ge] : 2.0f;    // pad: out of domain
            int p = e / 3, c = e - p * 3;
            if      (c == 0) t_x[p] = v;
            else if (c == 1) t_y[p] = v;
            else             t_z[p] = v;
        }
        __syncthreads();

        // two independent points per thread: tid and tid+1024
        const int p0 = base + tid;
        const int p1 = base + tid + THREADS;
        float x0 = t_x[tid],           y0 = t_y[tid],           z0 = t_z[tid];
        float x1 = t_x[tid + THREADS], y1 = t_y[tid + THREADS], z1 = t_z[tid + THREADS];

        if (p0 < L)
            *reinterpret_cast<float4*>(out + 4 * (size_t)p0) =
                make_float4(x0, y0, z0, 0.0f);
        if (p1 < L)
            *reinterpret_cast<float4*>(out + 4 * (size_t)p1) =
                make_float4(x1, y1, z1, 0.0f);

        int c0 = (cell_of(z0) * GC + cell_of(y0)) * GC + cell_of(x0);
        int c1 = (cell_of(z1) * GC + cell_of(y1)) * GC + cell_of(x1);
        unsigned int cn0 = (p0 < L) ? (unsigned int)s_cnt[c0] : 0u;
        unsigned int cn1 = (p1 < L) ? (unsigned int)s_cnt[c1] : 0u;

        if (cn0) {
            int  lim = (cn0 == 255u) ? B : (int)cn0;
            bool all = (cn0 == 255u);
            for (int k = 0; k < lim; ++k) {
                int r = all ? k : (int)s_list[c0 * KCAP + k];
                float dx = x0 - srx[r], dy = y0 - sry[r], dz = z0 - srz[r];
                float d2 = dx * dx + dy * dy + dz * dz;
                unsigned long long key =
                    ~((((unsigned long long)__float_as_uint(d2)) << 32) |
                      (unsigned long long)(unsigned int)p0);
                if (key > s_best[r]) atomicMax(&s_best[r], key);
            }
        }
        if (cn1) {
            int  lim = (cn1 == 255u) ? B : (int)cn1;
            bool all = (cn1 == 255u);
            for (int k = 0; k < lim; ++k) {
                int r = all ? k : (int)s_list[c1 * KCAP + k];
                float dx = x1 - srx[r], dy = y1 - sry[r], dz = z1 - srz[r];
                float d2 = dx * dx + dy * dy + dz * dz;
                unsigned long long key =
                    ~((((unsigned long long)__float_as_uint(d2)) << 32) |
                      (unsigned long long)(unsigned int)p1);
                if (key > s_best[r]) atomicMax(&s_best[r], key);
            }
        }
    }
    __syncthreads();   // all smem atomics visible (also for zero-tile blocks)

    // ---- one global merge per block (<=128 atomics) ----
    if (tid < B) atomicMax(&g_best[tid], s_best[tid]);

    // ---- last-finishing block finalizes ----
    __threadfence();
    __syncthreads();
    __shared__ bool is_last;
    if (tid == 0) is_last = (atomicAdd(&g_done, 1u) == GRID - 1);
    __syncthreads();
    if (!is_last) return;

    if (tid < B) {
        // authoritative read (atomicMax with identity 0 leaves value intact)
        unsigned long long key = atomicMax(&g_best[tid], 0ull);
        unsigned int idx = ~((unsigned int)(key & 0xffffffffull));
        float* cp = out + 4 * (size_t)L;
        cp[3 * tid + 0] = pts[3 * idx + 0];
        cp[3 * tid + 1] = pts[3 * idx + 1];
        cp[3 * tid + 2] = pts[3 * idx + 2];
        out[4 * (size_t)L + 3 * B + tid] = (float)idx;   // min_index as float
        out[4 * (size_t)idx + 3] = 1.0f;                 // one-hot scatter
        g_best[tid] = 0ull;                              // reset for next replay
    }
    if (tid == 0) {
        if (B > 1) out[3] = 1.0f;        // reference quirk: index 0 also set
        g_done = 0u;                     // reset for next replay
    }
}

// ---------------------------------------------------------------------------
extern "C" void kernel_launch(void* const* d_in, const int* in_sizes, int n_in,
                              void* d_out, int out_size)
{
    const float* pts  = (const float*)d_in[0];   // mesh_3D flattened [L,3]
    const float* recv = (const float*)d_in[1];   // receiver_pos [B,3]
    float* out = (float*)d_out;

    int L = in_sizes[0] / 3;   // 1,000,000
    int B = in_sizes[1] / 3;   // 128

    fused_kernel<<<GRID, THREADS>>>(pts, recv, out, L, B);
}

// round 14
// speedup vs baseline: 2.1983x; 2.1983x over previous
#include <cuda_runtime.h>
#include <cstdint>

// ============================================================================
// OneHotEncoding — single kernel, zero grid barriers, block-local argmin.
//
// R12/R13 lesson: per-tile __syncthreads() around smem point-staging
// resynchronizes all warps into the same stall chain => latency never hidden
// (issue ~36%, 2x slowdowns with bigger bodies). R4 evidence: direct-from-
// global grid-stride streaming with 4 pts/thread (3x LDG.128) and NO barriers
// was fast. This round = R10's proven probe+build prologue + R4's proven
// barrier-free stream + block-local s_best merge.
//
// Output layout (float32):
//   [0, 4L)            input_tensor: per point (x, y, z, one_hot)
//   [4L, 4L+3B)        closest_points [B,3]
//   [4L+3B, 4L+4B)     min_index as float [B]
//
// Merge key: ~((u64)d2bits<<32 | idx), combined with max.
//   - zero-initialized .bss g_best IS the identity (no init pass)
//   - max of complement == min (d2, idx) => first-index tie-break
//   - probe seed ~(probe_d2<<32 | 0xFFFFFFFF) is provably below the true
//     winner's key (true d2 <= probe d2; real idx < 0xFFFFFFFF): filters only.
//   - finalize resets g_best/g_done to 0 => graph-replay deterministic.
//
// Candidate table: receiver r's box [r-UB, r+UB]^3 (UB = exact distance to a
// real sampled point) covers r's true NN. Cells with >KCAP receivers get
// sentinel 255 => brute-force all B there. Unconditionally correct.
// ============================================================================

#define GC       16
#define CELLS    (GC * GC * GC)        // 4096
#define MAXB     128
#define GRID     152
#define THREADS  1024
#define KCAP     5                     // candidate list slots per cell
#define PROBE_N  1024                  // sample points for UB probe

__device__ unsigned long long g_best[MAXB];   // complemented keys; 0 = identity
__device__ unsigned int       g_done;         // zero-init; self-resetting

__device__ __forceinline__ int cell_of(float x) {
    int c = __float2int_rd(x * (float)GC);
    c = c < 0 ? 0 : c;
    return c > GC - 1 ? GC - 1 : c;
}

// ---------------------------------------------------------------------------
__global__ void __launch_bounds__(THREADS, 1)
fused_kernel(const float* __restrict__ pts, const float* __restrict__ recv,
             float* __restrict__ out, int L, int B)
{
    const int tid  = threadIdx.x;
    const int lane = tid & 31;
    const int wid  = tid >> 5;
    const int bid  = blockIdx.x;

    __shared__ float srx[MAXB], sry[MAXB], srz[MAXB];
    __shared__ float s_ub[MAXB];                       // probe min d2 per recv
    __shared__ unsigned long long s_best[MAXB];        // block-local keys
    __shared__ unsigned char s_list[CELLS * KCAP];     // 20 KB
    __shared__ unsigned char s_cnt[CELLS];             // 4 KB (255 = overflow)
    // scratch: probe SoA (12 KB) then cnt32 (16 KB)
    __shared__ __align__(16) unsigned char s_scratch[16384];

    // ---- stage receivers ----
    if (tid < B) {
        srx[tid] = recv[3 * tid + 0];
        sry[tid] = recv[3 * tid + 1];
        srz[tid] = recv[3 * tid + 2];
    }

    // ---- stage probe samples SoA into scratch ----
    float* s_px = reinterpret_cast<float*>(s_scratch);
    float* s_py = s_px + PROBE_N;
    float* s_pz = s_py + PROBE_N;
    const int n  = (L < PROBE_N) ? L : PROBE_N;
    const int n3 = n * 3;
#pragma unroll
    for (int j = 0; j < 3; ++j) {
        int e = tid + j * THREADS;                 // [0, 3072)
        float v = (e < n3) ? pts[e] : 1.0e30f;
        int p = e / 3, c = e - p * 3;
        if      (c == 0) s_px[p] = v;
        else if (c == 1) s_py[p] = v;
        else             s_pz[p] = v;
    }
    __syncthreads();

    // ---- UB probe: warp wid owns receivers [4*wid, 4*wid+4) ----
    {
        const int rbase = wid * 4;
        float rx[4], ry[4], rz[4], bd[4];
#pragma unroll
        for (int k = 0; k < 4; ++k) {
            int rb = rbase + k;
            rx[k] = (rb < B) ? srx[rb] : 0.f;
            ry[k] = (rb < B) ? sry[rb] : 0.f;
            rz[k] = (rb < B) ? srz[rb] : 0.f;
            bd[k] = 3.4e38f;
        }
#pragma unroll 4
        for (int j = 0; j < PROBE_N / 32; ++j) {
            int i = lane + 32 * j;
            float px = s_px[i];
            float py = s_py[i];
            float pz = s_pz[i];
#pragma unroll
            for (int k = 0; k < 4; ++k) {
                float dx = px - rx[k];
                float dy = py - ry[k];
                float dz = pz - rz[k];
                float d2 = dx * dx + dy * dy + dz * dz;
                bd[k] = fminf(bd[k], d2);
            }
        }
#pragma unroll
        for (int k = 0; k < 4; ++k) {
#pragma unroll
            for (int m = 16; m > 0; m >>= 1)
                bd[k] = fminf(bd[k], __shfl_xor_sync(0xffffffffu, bd[k], m));
            if (lane == 0 && (rbase + k) < B) {
                s_ub[rbase + k] = bd[k];
                // seed: <= true winner's key (d2 >= true d2, idx field maximal)
                s_best[rbase + k] =
                    ~((((unsigned long long)__float_as_uint(bd[k])) << 32) |
                      0xFFFFFFFFull);
            }
        }
    }
    __syncthreads();

    // ---- zero cnt32 (reuses scratch) ----
    unsigned int* cnt32 = reinterpret_cast<unsigned int*>(s_scratch);
#pragma unroll
    for (int j = 0; j < CELLS / THREADS; ++j) cnt32[tid + j * THREADS] = 0u;
    __syncthreads();

    // ---- build candidate lists (receiver-major, smem atomics) ----
    if (tid < B) {
        float ub = sqrtf(s_ub[tid]) * 1.0001f + 1e-7f;   // ulp guard
        float rx = srx[tid], ry = sry[tid], rz = srz[tid];
        int lx = cell_of(rx - ub), hx = cell_of(rx + ub);
        int ly = cell_of(ry - ub), hy = cell_of(ry + ub);
        int lz = cell_of(rz - ub), hz = cell_of(rz + ub);
        for (int zz = lz; zz <= hz; ++zz)
            for (int yy = ly; yy <= hy; ++yy)
                for (int xx = lx; xx <= hx; ++xx) {
                    int c = (zz * GC + yy) * GC + xx;
                    unsigned int pos = atomicAdd(&cnt32[c], 1u);
                    if (pos < KCAP) s_list[c * KCAP + pos] = (unsigned char)tid;
                }
    }
    __syncthreads();

    // ---- compact counts to u8 with overflow sentinel ----
#pragma unroll
    for (int j = 0; j < CELLS / THREADS; ++j) {
        int c = tid + j * THREADS;
        unsigned int v = cnt32[c];
        s_cnt[c] = (v > KCAP) ? (unsigned char)255 : (unsigned char)v;
    }
    __syncthreads();

    // ---- streaming pass: BARRIER-FREE grid-stride, 4 pts/thread ----
    // Direct 3x LDG.128 from pts (aligned: 48*g bytes); warps free-run and
    // desynchronize so memory latency overlaps across the 32 warps/SM.
    {
        const int nGrp   = (L + 3) >> 2;                 // groups of 4 points
        const int stride = GRID * THREADS;

        for (int g = bid * THREADS + tid; g < nGrp; g += stride) {
            const int p0 = 4 * g;
            float x[4], y[4], z[4];
            if (p0 + 3 < L) {                            // fast path
                const float4* src = reinterpret_cast<const float4*>(pts + 3 * p0);
                float4 a = src[0], bq = src[1], c = src[2];
                x[0]=a.x;  y[0]=a.y;  z[0]=a.z;
                x[1]=a.w;  y[1]=bq.x; z[1]=bq.y;
                x[2]=bq.z; y[2]=bq.w; z[2]=c.x;
                x[3]=c.y;  y[3]=c.z;  z[3]=c.w;
            } else {
#pragma unroll
                for (int j = 0; j < 4; ++j) {
                    int p = p0 + j;
                    x[j] = (p < L) ? pts[3 * p + 0] : 2.0f;  // never listed
                    y[j] = (p < L) ? pts[3 * p + 1] : 2.0f;
                    z[j] = (p < L) ? pts[3 * p + 2] : 2.0f;
                }
            }

#pragma unroll
            for (int j = 0; j < 4; ++j) {
                const int p = p0 + j;
                if (p >= L) break;
                *reinterpret_cast<float4*>(out + 4 * (size_t)p) =
                    make_float4(x[j], y[j], z[j], 0.0f);

                int c = (cell_of(z[j]) * GC + cell_of(y[j])) * GC + cell_of(x[j]);
                unsigned int cn = s_cnt[c];              // LDS
                if (cn) {
                    int  lim = (cn == 255u) ? B : (int)cn;
                    bool all = (cn == 255u);
                    for (int k = 0; k < lim; ++k) {
                        int r = all ? k : (int)s_list[c * KCAP + k];
                        float dx = x[j] - srx[r];
                        float dy = y[j] - sry[r];
                        float dz = z[j] - srz[r];
                        float d2 = dx * dx + dy * dy + dz * dz;
                        unsigned long long key =
                            ~((((unsigned long long)__float_as_uint(d2)) << 32) |
                              (unsigned long long)(unsigned int)p);
                        // LDS guard block-coherent; smem atomic authoritative
                        if (key > s_best[r]) atomicMax(&s_best[r], key);
                    }
                }
            }
        }
    }
    __syncthreads();   // all smem atomics visible

    // ---- one global merge per block (<=128 atomics) ----
    if (tid < B) atomicMax(&g_best[tid], s_best[tid]);

    // ---- last-finishing block finalizes ----
    __threadfence();
    __syncthreads();
    __shared__ bool is_last;
    if (tid == 0) is_last = (atomicAdd(&g_done, 1u) == GRID - 1);
    __syncthreads();
    if (!is_last) return;

    if (tid < B) {
        // authoritative read (atomicMax with identity 0 leaves value intact)
        unsigned long long key = atomicMax(&g_best[tid], 0ull);
        unsigned int idx = ~((unsigned int)(key & 0xffffffffull));
        float* cp = out + 4 * (size_t)L;
        cp[3 * tid + 0] = pts[3 * idx + 0];
        cp[3 * tid + 1] = pts[3 * idx + 1];
        cp[3 * tid + 2] = pts[3 * idx + 2];
        out[4 * (size_t)L + 3 * B + tid] = (float)idx;   // min_index as float
        out[4 * (size_t)idx + 3] = 1.0f;                 // one-hot scatter
        g_best[tid] = 0ull;                              // reset for next replay
    }
    if (tid == 0) {
        if (B > 1) out[3] = 1.0f;        // reference quirk: index 0 also set
        g_done = 0u;                     // reset for next replay
    }
}

// ---------------------------------------------------------------------------
extern "C" void kernel_launch(void* const* d_in, const int* in_sizes, int n_in,
                              void* d_out, int out_size)
{
    const float* pts  = (const float*)d_in[0];   // mesh_3D flattened [L,3]
    const float* recv = (const float*)d_in[1];   // receiver_pos [B,3]
    float* out = (float*)d_out;

    int L = in_sizes[0] / 3;   // 1,000,000
    int B = in_sizes[1] / 3;   // 128

    fused_kernel<<<GRID, THREADS>>>(pts, recv, out, L, B);
}

// round 15
// speedup vs baseline: 2.6822x; 1.2201x over previous
#include <cuda_runtime.h>
#include <cstdint>

// ============================================================================
// OneHotEncoding — single kernel, zero grid barriers, block-local argmin.
//
// R14 base (barrier-free stream). R15 changes, aimed at the measured
// instruction/divergence ceiling (issue=47%, nothing else saturated):
//  1. Sphere-exact cell filter in the candidate build (cell admitted only if
//     exact min-dist(receiver, cell cuboid)^2 <= UB^2). Halves list entries
//     AND the warp-max candidate count (divergent loop pays max, not mean).
//  2. 8 points/thread: 125K groups < 155.6K threads => every thread runs at
//     most ONE group (kills the 1.6x grid-stride imbalance), ILP=8.
//  3. Stream cell_of trimmed to mul+min+cvt (coords in [0,1) by construction;
//     full clamp retained in probe/build where r-UB can go negative).
//
// Output layout (float32):
//   [0, 4L)            input_tensor: per point (x, y, z, one_hot)
//   [4L, 4L+3B)        closest_points [B,3]
//   [4L+3B, 4L+4B)     min_index as float [B]
//
// Merge key: ~((u64)d2bits<<32 | idx), combined with max.
//   - zero-initialized .bss g_best IS the identity (no init pass)
//   - max of complement == min (d2, idx) => first-index tie-break
//   - probe seed ~(probe_d2<<32 | 0xFFFFFFFF) is provably below the true
//     winner's key: filters only, never decides.
//   - finalize resets g_best/g_done to 0 => graph-replay deterministic.
//
// Candidate table: cell admitted for receiver r iff min-dist(r, cell)^2 <=
// guarded UB^2 (UB = exact distance to a real sampled point). The true NN's
// cell always qualifies (min-dist <= d_true <= UB). Cells with >KCAP
// receivers get sentinel 255 => brute-force all B there. Unconditionally
// correct.
// ============================================================================

#define GC       16
#define CELLS    (GC * GC * GC)        // 4096
#define MAXB     128
#define GRID     152
#define THREADS  1024
#define KCAP     5                     // candidate list slots per cell
#define PROBE_N  1024                  // sample points for UB probe

__device__ unsigned long long g_best[MAXB];   // complemented keys; 0 = identity
__device__ unsigned int       g_done;         // zero-init; self-resetting

// full-clamp version (probe/build: r-UB may leave [0,1))
__device__ __forceinline__ int cell_of(float x) {
    int c = __float2int_rd(x * (float)GC);
    c = c < 0 ? 0 : c;
    return c > GC - 1 ? GC - 1 : c;
}
// stream version: data coords are in [0,1) => only upper guard needed
__device__ __forceinline__ int cell_fast(float x) {
    return (int)fminf(x * (float)GC, (float)(GC - 1));
}

// ---------------------------------------------------------------------------
__global__ void __launch_bounds__(THREADS, 1)
fused_kernel(const float* __restrict__ pts, const float* __restrict__ recv,
             float* __restrict__ out, int L, int B)
{
    const int tid  = threadIdx.x;
    const int lane = tid & 31;
    const int wid  = tid >> 5;
    const int bid  = blockIdx.x;

    __shared__ float srx[MAXB], sry[MAXB], srz[MAXB];
    __shared__ float s_ub[MAXB];                       // probe min d2 per recv
    __shared__ unsigned long long s_best[MAXB];        // block-local keys
    __shared__ unsigned char s_list[CELLS * KCAP];     // 20 KB
    __shared__ unsigned char s_cnt[CELLS];             // 4 KB (255 = overflow)
    // scratch: probe SoA (12 KB) then cnt32 (16 KB)
    __shared__ __align__(16) unsigned char s_scratch[16384];

    // ---- stage receivers ----
    if (tid < B) {
        srx[tid] = recv[3 * tid + 0];
        sry[tid] = recv[3 * tid + 1];
        srz[tid] = recv[3 * tid + 2];
    }

    // ---- stage probe samples SoA into scratch ----
    float* s_px = reinterpret_cast<float*>(s_scratch);
    float* s_py = s_px + PROBE_N;
    float* s_pz = s_py + PROBE_N;
    const int n  = (L < PROBE_N) ? L : PROBE_N;
    const int n3 = n * 3;
#pragma unroll
    for (int j = 0; j < 3; ++j) {
        int e = tid + j * THREADS;                 // [0, 3072)
        float v = (e < n3) ? pts[e] : 1.0e30f;
        int p = e / 3, c = e - p * 3;
        if      (c == 0) s_px[p] = v;
        else if (c == 1) s_py[p] = v;
        else             s_pz[p] = v;
    }
    __syncthreads();

    // ---- UB probe: warp wid owns receivers [4*wid, 4*wid+4) ----
    {
        const int rbase = wid * 4;
        float rx[4], ry[4], rz[4], bd[4];
#pragma unroll
        for (int k = 0; k < 4; ++k) {
            int rb = rbase + k;
            rx[k] = (rb < B) ? srx[rb] : 0.f;
            ry[k] = (rb < B) ? sry[rb] : 0.f;
            rz[k] = (rb < B) ? srz[rb] : 0.f;
            bd[k] = 3.4e38f;
        }
#pragma unroll 4
        for (int j = 0; j < PROBE_N / 32; ++j) {
            int i = lane + 32 * j;
            float px = s_px[i];
            float py = s_py[i];
            float pz = s_pz[i];
#pragma unroll
            for (int k = 0; k < 4; ++k) {
                float dx = px - rx[k];
                float dy = py - ry[k];
                float dz = pz - rz[k];
                float d2 = dx * dx + dy * dy + dz * dz;
                bd[k] = fminf(bd[k], d2);
            }
        }
#pragma unroll
        for (int k = 0; k < 4; ++k) {
#pragma unroll
            for (int m = 16; m > 0; m >>= 1)
                bd[k] = fminf(bd[k], __shfl_xor_sync(0xffffffffu, bd[k], m));
            if (lane == 0 && (rbase + k) < B) {
                s_ub[rbase + k] = bd[k];
                // seed: <= true winner's key (d2 >= true d2, idx field maximal)
                s_best[rbase + k] =
                    ~((((unsigned long long)__float_as_uint(bd[k])) << 32) |
                      0xFFFFFFFFull);
            }
        }
    }
    __syncthreads();

    // ---- zero cnt32 (reuses scratch) ----
    unsigned int* cnt32 = reinterpret_cast<unsigned int*>(s_scratch);
#pragma unroll
    for (int j = 0; j < CELLS / THREADS; ++j) cnt32[tid + j * THREADS] = 0u;
    __syncthreads();

    // ---- build candidate lists (receiver-major, sphere-exact filter) ----
    if (tid < B) {
        float ub  = sqrtf(s_ub[tid]) * 1.0001f + 1e-7f;  // ulp guard
        float ub2 = ub * ub;
        const float h = 1.0f / (float)GC;
        float rx = srx[tid], ry = sry[tid], rz = srz[tid];
        int lx = cell_of(rx - ub), hx = cell_of(rx + ub);
        int ly = cell_of(ry - ub), hy = cell_of(ry + ub);
        int lz = cell_of(rz - ub), hz = cell_of(rz + ub);
        for (int zz = lz; zz <= hz; ++zz) {
            float dz = fmaxf(fmaxf((float)zz * h - rz, rz - (float)(zz + 1) * h), 0.f);
            for (int yy = ly; yy <= hy; ++yy) {
                float dy = fmaxf(fmaxf((float)yy * h - ry, ry - (float)(yy + 1) * h), 0.f);
                float dzy = dz * dz + dy * dy;
                for (int xx = lx; xx <= hx; ++xx) {
                    float dx = fmaxf(fmaxf((float)xx * h - rx, rx - (float)(xx + 1) * h), 0.f);
                    if (dzy + dx * dx <= ub2) {          // sphere-exact test
                        int c = (zz * GC + yy) * GC + xx;
                        unsigned int pos = atomicAdd(&cnt32[c], 1u);
                        if (pos < KCAP) s_list[c * KCAP + pos] = (unsigned char)tid;
                    }
                }
            }
        }
    }
    __syncthreads();

    // ---- compact counts to u8 with overflow sentinel ----
#pragma unroll
    for (int j = 0; j < CELLS / THREADS; ++j) {
        int c = tid + j * THREADS;
        unsigned int v = cnt32[c];
        s_cnt[c] = (v > KCAP) ? (unsigned char)255 : (unsigned char)v;
    }
    __syncthreads();

    // ---- streaming pass: BARRIER-FREE, 8 pts/thread, one pass/thread ----
    {
        const int nGrp   = (L + 7) >> 3;                 // 125000 for L=1e6
        const int stride = GRID * THREADS;

        for (int g = bid * THREADS + tid; g < nGrp; g += stride) {
            const int p0 = 8 * g;
            float x[8], y[8], z[8];
            if (p0 + 8 <= L) {                           // fast path: 6x LDG.128
                const float4* src = reinterpret_cast<const float4*>(pts + 3 * p0);
                float4 v0 = src[0], v1 = src[1], v2 = src[2],
                       v3 = src[3], v4 = src[4], v5 = src[5];
                x[0]=v0.x; y[0]=v0.y; z[0]=v0.z;
                x[1]=v0.w; y[1]=v1.x; z[1]=v1.y;
                x[2]=v1.z; y[2]=v1.w; z[2]=v2.x;
                x[3]=v2.y; y[3]=v2.z; z[3]=v2.w;
                x[4]=v3.x; y[4]=v3.y; z[4]=v3.z;
                x[5]=v3.w; y[5]=v4.x; z[5]=v4.y;
                x[6]=v4.z; y[6]=v4.w; z[6]=v5.x;
                x[7]=v5.y; y[7]=v5.z; z[7]=v5.w;
            } else {
#pragma unroll
                for (int j = 0; j < 8; ++j) {
                    int p = p0 + j;
                    x[j] = (p < L) ? pts[3 * p + 0] : 0.5f;  // pad (guarded below)
                    y[j] = (p < L) ? pts[3 * p + 1] : 0.5f;
                    z[j] = (p < L) ? pts[3 * p + 2] : 0.5f;
                }
            }

            float4* obase = reinterpret_cast<float4*>(out) + p0;
#pragma unroll
            for (int j = 0; j < 8; ++j) {
                const int p = p0 + j;
                if (p >= L) break;
                obase[j] = make_float4(x[j], y[j], z[j], 0.0f);

                int c = (cell_fast(z[j]) * GC + cell_fast(y[j])) * GC
                        + cell_fast(x[j]);
                unsigned int cn = s_cnt[c];              // LDS
                if (cn) {
                    int  lim = (cn == 255u) ? B : (int)cn;
                    bool all = (cn == 255u);
                    for (int k = 0; k < lim; ++k) {
                        int r = all ? k : (int)s_list[c * KCAP + k];
                        float dx = x[j] - srx[r];
                        float dy = y[j] - sry[r];
                        float dz = z[j] - srz[r];
                        float d2 = dx * dx + dy * dy + dz * dz;
                        unsigned long long key =
                            ~((((unsigned long long)__float_as_uint(d2)) << 32) |
                              (unsigned long long)(unsigned int)p);
                        // LDS guard block-coherent; smem atomic authoritative
                        if (key > s_best[r]) atomicMax(&s_best[r], key);
                    }
                }
            }
        }
    }
    __syncthreads();   // all smem atomics visible

    // ---- one global merge per block (<=128 atomics) ----
    if (tid < B) atomicMax(&g_best[tid], s_best[tid]);

    // ---- last-finishing block finalizes ----
    __threadfence();
    __syncthreads();
    __shared__ bool is_last;
    if (tid == 0) is_last = (atomicAdd(&g_done, 1u) == GRID - 1);
    __syncthreads();
    if (!is_last) return;

    if (tid < B) {
        // authoritative read (atomicMax with identity 0 leaves value intact)
        unsigned long long key = atomicMax(&g_best[tid], 0ull);
        unsigned int idx = ~((unsigned int)(key & 0xffffffffull));
        float* cp = out + 4 * (size_t)L;
        cp[3 * tid + 0] = pts[3 * idx + 0];
        cp[3 * tid + 1] = pts[3 * idx + 1];
        cp[3 * tid + 2] = pts[3 * idx + 2];
        out[4 * (size_t)L + 3 * B + tid] = (float)idx;   // min_index as float
        out[4 * (size_t)idx + 3] = 1.0f;                 // one-hot scatter
        g_best[tid] = 0ull;                              // reset for next replay
    }
    if (tid == 0) {
        if (B > 1) out[3] = 1.0f;        // reference quirk: index 0 also set
        g_done = 0u;                     // reset for next replay
    }
}

// ---------------------------------------------------------------------------
extern "C" void kernel_launch(void* const* d_in, const int* in_sizes, int n_in,
                              void* d_out, int out_size)
{
    const float* pts  = (const float*)d_in[0];   // mesh_3D flattened [L,3]
    const float* recv = (const float*)d_in[1];   // receiver_pos [B,3]
    float* out = (float*)d_out;

    int L = in_sizes[0] / 3;   // 1,000,000
    int B = in_sizes[1] / 3;   // 128

    fused_kernel<<<GRID, THREADS>>>(pts, recv, out, L, B);
}